// round 1
// baseline (speedup 1.0000x reference)
#include <cuda_runtime.h>

// ---------------------------------------------------------------------------
// MSMLMultiHeadAttention (stage-1 windowed linear attention), B=2, N=16384,
// C=256, WIN=16, W=1024. Only windows w<64 reach the output slice.
//
// Pipeline:
//  1) gemm_act: phi_k = phi(input@Wk+bk) for all 32768 tokens
//               phi_q = phi(input@Wq+bq) for first 1024 tokens/batch
//     where phi(z) = z+2 (z>0) else exp(z)+1   [double-ELU collapses]
//  2) kv:  KV[b,m] = Phi_k[b,:,m,:]^T V[b,:,m,:]  (K=1024, stride-16 rows)
//          stored as KVcat[b][c][m*256+d]  (256 x 4096 per batch)
//  3) att: R = phi_q (1024x256) @ KVcat (256x4096) per batch,
//          epilogue: out[b, w*256+n*16+m, d] = R[w*16+n][m*256+d] + p(b,w,n,m)
// ---------------------------------------------------------------------------

#define BK 16

__device__ float g_phiK[2L * 16384 * 256];
__device__ float g_phiQ[2L * 1024 * 256];
__device__ float g_KV[2L * 256 * 4096];

__device__ __forceinline__ float phi_act(float z) {
    return z > 0.f ? z + 2.f : __expf(z) + 1.f;
}

#define INNER_PRODUCT()                                              \
    _Pragma("unroll")                                                \
    for (int kk = 0; kk < BK; kk++) {                                \
        float a[8], bvals[8];                                        \
        *(float4*)&a[0]     = *(float4*)&As[kk][ty * 8];             \
        *(float4*)&a[4]     = *(float4*)&As[kk][ty * 8 + 4];         \
        *(float4*)&bvals[0] = *(float4*)&Bs[kk][tx * 8];             \
        *(float4*)&bvals[4] = *(float4*)&Bs[kk][tx * 8 + 4];         \
        _Pragma("unroll")                                            \
        for (int i = 0; i < 8; i++)                                  \
            _Pragma("unroll")                                        \
            for (int j = 0; j < 8; j++)                              \
                acc[i][j] += a[i] * bvals[j];                        \
    }

// ---------------------------------------------------------------------------
// Kernel 1: C = phi(X @ W + bias).  X rows per batch given by gridDim.x*128.
// gridDim = (rows/128, 2, B). K = N = 256 fixed.
// ---------------------------------------------------------------------------
__global__ __launch_bounds__(256) void gemm_act_kernel(
    const float* __restrict__ X, long xb,
    const float* __restrict__ W, const float* __restrict__ bias,
    float* __restrict__ out, long ob)
{
    __shared__ __align__(16) float As[BK][132];  // padded transpose tile
    __shared__ __align__(16) float Bs[BK][128];
    const int tid = threadIdx.x;
    const int tx = tid & 15, ty = tid >> 4;
    const long r0 = (long)blockIdx.x * 128;
    const int  c0 = blockIdx.y * 128;
    const float* Xb = X + (long)blockIdx.z * xb + r0 * 256;
    float*       Ob = out + (long)blockIdx.z * ob + r0 * 256 + c0;

    float acc[8][8];
#pragma unroll
    for (int i = 0; i < 8; i++)
#pragma unroll
        for (int j = 0; j < 8; j++) acc[i][j] = 0.f;

    for (int k0 = 0; k0 < 256; k0 += BK) {
#pragma unroll
        for (int i = 0; i < 2; i++) {
            int f4 = tid + i * 256;
            int row = f4 >> 2, kc = (f4 & 3) * 4;
            float4 v = *(const float4*)(Xb + row * 256 + k0 + kc);
            As[kc + 0][row] = v.x; As[kc + 1][row] = v.y;
            As[kc + 2][row] = v.z; As[kc + 3][row] = v.w;
        }
#pragma unroll
        for (int i = 0; i < 2; i++) {
            int f4 = tid + i * 256;
            int kr = f4 >> 5, nc = (f4 & 31) * 4;
            *(float4*)&Bs[kr][nc] =
                *(const float4*)(W + (long)(k0 + kr) * 256 + c0 + nc);
        }
        __syncthreads();
        INNER_PRODUCT();
        __syncthreads();
    }

    float bb[8];
    *(float4*)&bb[0] = *(const float4*)(bias + c0 + tx * 8);
    *(float4*)&bb[4] = *(const float4*)(bias + c0 + tx * 8 + 4);
#pragma unroll
    for (int i = 0; i < 8; i++) {
#pragma unroll
        for (int j4 = 0; j4 < 8; j4 += 4) {
            float4 o;
            o.x = phi_act(acc[i][j4 + 0] + bb[j4 + 0]);
            o.y = phi_act(acc[i][j4 + 1] + bb[j4 + 1]);
            o.z = phi_act(acc[i][j4 + 2] + bb[j4 + 2]);
            o.w = phi_act(acc[i][j4 + 3] + bb[j4 + 3]);
            *(float4*)(Ob + (long)(ty * 8 + i) * 256 + tx * 8 + j4) = o;
        }
    }
}

// ---------------------------------------------------------------------------
// Kernel 2: KV[b,m][c][d] = sum_w phiK[b, w*16+m, c] * V[b, w*16+m, d]
// gridDim = (2, 2, 32): x tiles c, y tiles d, z = b*16+m. K = 1024.
// Output: g_KV[(b*256 + c)*4096 + m*256 + d]
// ---------------------------------------------------------------------------
__global__ __launch_bounds__(256) void kv_kernel(const float* __restrict__ V)
{
    __shared__ __align__(16) float As[BK][128];
    __shared__ __align__(16) float Bs[BK][128];
    const int tid = threadIdx.x;
    const int tx = tid & 15, ty = tid >> 4;
    const int bm = blockIdx.z, b = bm >> 4, m = bm & 15;
    const long base = ((long)b * 16384 + m) * 256;
    const int c0 = blockIdx.x * 128, d0 = blockIdx.y * 128;

    float acc[8][8];
#pragma unroll
    for (int i = 0; i < 8; i++)
#pragma unroll
        for (int j = 0; j < 8; j++) acc[i][j] = 0.f;

    for (int k0 = 0; k0 < 1024; k0 += BK) {
#pragma unroll
        for (int i = 0; i < 2; i++) {
            int f4 = tid + i * 256;
            int kr = f4 >> 5, cc = (f4 & 31) * 4;
            long roff = base + (long)(k0 + kr) * 4096;  // token stride 16*256
            *(float4*)&As[kr][cc] = *(const float4*)(g_phiK + roff + c0 + cc);
            *(float4*)&Bs[kr][cc] = *(const float4*)(V + roff + d0 + cc);
        }
        __syncthreads();
        INNER_PRODUCT();
        __syncthreads();
    }

#pragma unroll
    for (int i = 0; i < 8; i++) {
        int c = c0 + ty * 8 + i;
        float* dst = g_KV + ((long)b * 256 + c) * 4096 + m * 256 + d0 + tx * 8;
#pragma unroll
        for (int j4 = 0; j4 < 8; j4 += 4) {
            float4 o = make_float4(acc[i][j4], acc[i][j4 + 1],
                                   acc[i][j4 + 2], acc[i][j4 + 3]);
            *(float4*)(dst + j4) = o;
        }
    }
}

// ---------------------------------------------------------------------------
// Kernel 3: R = phi_q (1024x256) @ KVcat (256x4096), permuted write + p bias.
// gridDim = (8, 32, 2): x tiles r (w*16+n), y tiles j (m*256+d), z = b.
// out[b, w*256+n*16+m, d] = R[r][j] + p(b,w,n,m)
// ---------------------------------------------------------------------------
__global__ __launch_bounds__(256) void att_kernel(
    const float* __restrict__ embed, const float* __restrict__ Wp,
    const float* __restrict__ bp, float* __restrict__ out)
{
    __shared__ __align__(16) float As[BK][132];
    __shared__ __align__(16) float Bs[BK][128];
    const int tid = threadIdx.x;
    const int tx = tid & 15, ty = tid >> 4;
    const int b = blockIdx.z;
    const int r0 = blockIdx.x * 128;
    const int j0 = blockIdx.y * 128;
    const float* A    = g_phiQ + (long)b * 1024 * 256 + (long)r0 * 256;
    const float* Bmat = g_KV + (long)b * 256 * 4096;

    float acc[8][8];
#pragma unroll
    for (int i = 0; i < 8; i++)
#pragma unroll
        for (int j = 0; j < 8; j++) acc[i][j] = 0.f;

    for (int k0 = 0; k0 < 256; k0 += BK) {
#pragma unroll
        for (int i = 0; i < 2; i++) {
            int f4 = tid + i * 256;
            int row = f4 >> 2, kc = (f4 & 3) * 4;
            float4 v = *(const float4*)(A + row * 256 + k0 + kc);
            As[kc + 0][row] = v.x; As[kc + 1][row] = v.y;
            As[kc + 2][row] = v.z; As[kc + 3][row] = v.w;
        }
#pragma unroll
        for (int i = 0; i < 2; i++) {
            int f4 = tid + i * 256;
            int kr = f4 >> 5, nc = (f4 & 31) * 4;
            *(float4*)&Bs[kr][nc] =
                *(const float4*)(Bmat + (long)(k0 + kr) * 4096 + j0 + nc);
        }
        __syncthreads();
        INNER_PRODUCT();
        __syncthreads();
    }

    const float wp0 = Wp[0], wp1 = Wp[1], wp2 = Wp[2], bpv = bp[0];
    const int jb = j0 + tx * 8;      // column within [0,4096)
    const int m = jb >> 8;           // constant per thread (tile within one m)
    const int d = jb & 255;
#pragma unroll
    for (int i = 0; i < 8; i++) {
        int r = r0 + ty * 8 + i;
        int w = r >> 4, n = r & 15;
        const float* e = embed + ((((long)b * 1024 + w) * 16 + n) * 16 + m) * 3;
        float p = e[0] * wp0 + e[1] * wp1 + e[2] * wp2 + bpv;
        long t = (long)w * 256 + n * 16 + m;
        float* dst = out + ((long)b * 16384 + t) * 256 + d;
#pragma unroll
        for (int j4 = 0; j4 < 8; j4 += 4) {
            float4 o = make_float4(acc[i][j4] + p, acc[i][j4 + 1] + p,
                                   acc[i][j4 + 2] + p, acc[i][j4 + 3] + p);
            *(float4*)(dst + j4) = o;
        }
    }
}

// ---------------------------------------------------------------------------
// Inputs (metadata order): input, embed_qk, Wq, bq, Wk, bk, Wp, bp
// ---------------------------------------------------------------------------
extern "C" void kernel_launch(void* const* d_in, const int* in_sizes, int n_in,
                              void* d_out, int out_size)
{
    const float* input = (const float*)d_in[0];
    const float* embed = (const float*)d_in[1];
    const float* Wq    = (const float*)d_in[2];
    const float* bq    = (const float*)d_in[3];
    const float* Wk    = (const float*)d_in[4];
    const float* bk    = (const float*)d_in[5];
    const float* Wp    = (const float*)d_in[6];
    const float* bp    = (const float*)d_in[7];
    float* out = (float*)d_out;

    float* phiK; cudaGetSymbolAddress((void**)&phiK, g_phiK);
    float* phiQ; cudaGetSymbolAddress((void**)&phiQ, g_phiQ);

    const long BATCH = 16384L * 256;

    // phi_k for all tokens
    gemm_act_kernel<<<dim3(128, 2, 2), 256>>>(input, BATCH, Wk, bk, phiK, BATCH);
    // phi_q only for the first 1024 tokens per batch (w < 64)
    gemm_act_kernel<<<dim3(8, 2, 2), 256>>>(input, BATCH, Wq, bq, phiQ, 1024L * 256);
    // KV accumulation over all 1024 windows
    kv_kernel<<<dim3(2, 2, 32), 256>>>(input);
    // attention GEMM + positional bias + permuted output
    att_kernel<<<dim3(8, 32, 2), 256>>>(embed, Wp, bp, out);
}

// round 2
// speedup vs baseline: 1.1151x; 1.1151x over previous
#include <cuda_runtime.h>

// ---------------------------------------------------------------------------
// MSMLMultiHeadAttention stage-1 windowed linear attention. B=2, N=16384,
// C=256, WIN=16. Only windows w<64 reach the output slice.
// Round 2: packed fma.rn.f32x2 inner products (2x fp32 throughput),
// fused phi_q+phi_k GEMM launch, K-split kv with deterministic reduce.
// ---------------------------------------------------------------------------

#define BK 16
typedef unsigned long long u64;

__device__ float g_phiK[2L * 16384 * 256];
__device__ float g_phiQ[2L * 1024 * 256];
__device__ float g_KV[2L * 256 * 4096];
__device__ float g_KVp[4L * 2 * 256 * 4096];   // 4 K-slices of partial KV

__device__ __forceinline__ float phi_act(float z) {
    return z > 0.f ? z + 2.f : __expf(z) + 1.f;
}

// Packed-pair inner product: acc2[i][j] holds columns (2j, 2j+1) for row i.
#define INNER_PRODUCT2()                                                  \
    _Pragma("unroll")                                                     \
    for (int kk = 0; kk < BK; kk++) {                                     \
        float a[8];                                                       \
        u64 b2[4];                                                        \
        *(float4*)&a[0] = *(float4*)&As[kk][ty * 8];                      \
        *(float4*)&a[4] = *(float4*)&As[kk][ty * 8 + 4];                  \
        *(ulonglong2*)&b2[0] = *(ulonglong2*)&Bs[kk][tx * 8];             \
        *(ulonglong2*)&b2[2] = *(ulonglong2*)&Bs[kk][tx * 8 + 4];         \
        u64 a2[8];                                                        \
        _Pragma("unroll")                                                 \
        for (int i = 0; i < 8; i++)                                       \
            asm("mov.b64 %0, {%1, %1};" : "=l"(a2[i]) : "f"(a[i]));       \
        _Pragma("unroll")                                                 \
        for (int i = 0; i < 8; i++)                                       \
            _Pragma("unroll")                                             \
            for (int j = 0; j < 4; j++)                                   \
                asm("fma.rn.f32x2 %0, %1, %2, %0;"                        \
                    : "+l"(acc2[i][j]) : "l"(a2[i]), "l"(b2[j]));         \
    }

#define ACC_INIT()                                                        \
    u64 acc2[8][4];                                                       \
    _Pragma("unroll")                                                     \
    for (int i = 0; i < 8; i++)                                           \
        _Pragma("unroll")                                                 \
        for (int j = 0; j < 4; j++) acc2[i][j] = 0ULL;

#define UNPACK_ROW(i, o)                                                  \
    _Pragma("unroll")                                                     \
    for (int j = 0; j < 4; j++)                                           \
        asm("mov.b64 {%0, %1}, %2;"                                       \
            : "=f"(o[2 * j]), "=f"(o[2 * j + 1]) : "l"(acc2[i][j]));

// ---------------------------------------------------------------------------
// Kernel 1 (fused): phi_k for all 16384 rows/batch AND phi_q for first 1024.
// grid = (136, 2, 2): x<128 -> K path, x>=128 -> Q path. K = N = 256.
// ---------------------------------------------------------------------------
__global__ __launch_bounds__(256) void gemm_act_kernel(
    const float* __restrict__ X,
    const float* __restrict__ Wk, const float* __restrict__ bk,
    const float* __restrict__ Wq, const float* __restrict__ bq)
{
    __shared__ __align__(16) float As[BK][132];
    __shared__ __align__(16) float Bs[BK][128];
    const int tid = threadIdx.x;
    const int tx = tid & 15, ty = tid >> 4;
    const bool isQ = blockIdx.x >= 128;
    const long r0 = (long)(isQ ? blockIdx.x - 128 : blockIdx.x) * 128;
    const int  c0 = blockIdx.y * 128;
    const int  b  = blockIdx.z;
    const float* W    = isQ ? Wq : Wk;
    const float* bias = isQ ? bq : bk;
    const float* Xb = X + (long)b * 16384 * 256 + r0 * 256;
    float* Ob = (isQ ? g_phiQ + (long)b * 1024 * 256
                     : g_phiK + (long)b * 16384 * 256) + r0 * 256 + c0;

    ACC_INIT();

    for (int k0 = 0; k0 < 256; k0 += BK) {
#pragma unroll
        for (int i = 0; i < 2; i++) {
            int f4 = tid + i * 256;
            int row = f4 >> 2, kc = (f4 & 3) * 4;
            float4 v = *(const float4*)(Xb + row * 256 + k0 + kc);
            As[kc + 0][row] = v.x; As[kc + 1][row] = v.y;
            As[kc + 2][row] = v.z; As[kc + 3][row] = v.w;
        }
#pragma unroll
        for (int i = 0; i < 2; i++) {
            int f4 = tid + i * 256;
            int kr = f4 >> 5, nc = (f4 & 31) * 4;
            *(float4*)&Bs[kr][nc] =
                *(const float4*)(W + (long)(k0 + kr) * 256 + c0 + nc);
        }
        __syncthreads();
        INNER_PRODUCT2();
        __syncthreads();
    }

    float bb[8];
    *(float4*)&bb[0] = *(const float4*)(bias + c0 + tx * 8);
    *(float4*)&bb[4] = *(const float4*)(bias + c0 + tx * 8 + 4);
#pragma unroll
    for (int i = 0; i < 8; i++) {
        float o[8];
        UNPACK_ROW(i, o);
#pragma unroll
        for (int j = 0; j < 8; j++) o[j] = phi_act(o[j] + bb[j]);
        *(float4*)(Ob + (long)(ty * 8 + i) * 256 + tx * 8)     = *(float4*)&o[0];
        *(float4*)(Ob + (long)(ty * 8 + i) * 256 + tx * 8 + 4) = *(float4*)&o[4];
    }
}

// ---------------------------------------------------------------------------
// Kernel 2: partial KV over a 256-token K-slice.
// grid = (2, 2, 128): z = slice*32 + b*16 + m.  K-slice = 256 tokens.
// g_KVp[slice][(b*256+c)*4096 + m*256 + d]
// ---------------------------------------------------------------------------
__global__ __launch_bounds__(256) void kv_kernel(const float* __restrict__ V)
{
    __shared__ __align__(16) float As[BK][128];
    __shared__ __align__(16) float Bs[BK][128];
    const int tid = threadIdx.x;
    const int tx = tid & 15, ty = tid >> 4;
    const int zz = blockIdx.z;
    const int slice = zz >> 5, bm = zz & 31;
    const int b = bm >> 4, m = bm & 15;
    const long base = ((long)b * 16384 + m) * 256;
    const int c0 = blockIdx.x * 128, d0 = blockIdx.y * 128;

    ACC_INIT();

    const int kbeg = slice * 256;
    for (int k0 = kbeg; k0 < kbeg + 256; k0 += BK) {
#pragma unroll
        for (int i = 0; i < 2; i++) {
            int f4 = tid + i * 256;
            int kr = f4 >> 5, cc = (f4 & 31) * 4;
            long roff = base + (long)(k0 + kr) * 4096;  // token stride 16*256
            *(float4*)&As[kr][cc] = *(const float4*)(g_phiK + roff + c0 + cc);
            *(float4*)&Bs[kr][cc] = *(const float4*)(V + roff + d0 + cc);
        }
        __syncthreads();
        INNER_PRODUCT2();
        __syncthreads();
    }

    float* dstS = g_KVp + (long)slice * (2L * 256 * 4096);
#pragma unroll
    for (int i = 0; i < 8; i++) {
        int c = c0 + ty * 8 + i;
        float o[8];
        UNPACK_ROW(i, o);
        float* dst = dstS + ((long)b * 256 + c) * 4096 + m * 256 + d0 + tx * 8;
        *(float4*)(dst)     = *(float4*)&o[0];
        *(float4*)(dst + 4) = *(float4*)&o[4];
    }
}

// ---------------------------------------------------------------------------
// Kernel 2b: reduce the 4 K-slice partials into g_KV. 2M floats.
// ---------------------------------------------------------------------------
__global__ __launch_bounds__(256) void kv_reduce_kernel()
{
    const long S = 2L * 256 * 4096;
    long i = ((long)blockIdx.x * 256 + threadIdx.x) * 4;
    float4 a0 = *(float4*)(g_KVp + i);
    float4 a1 = *(float4*)(g_KVp + S + i);
    float4 a2 = *(float4*)(g_KVp + 2 * S + i);
    float4 a3 = *(float4*)(g_KVp + 3 * S + i);
    float4 r;
    r.x = (a0.x + a1.x) + (a2.x + a3.x);
    r.y = (a0.y + a1.y) + (a2.y + a3.y);
    r.z = (a0.z + a1.z) + (a2.z + a3.z);
    r.w = (a0.w + a1.w) + (a2.w + a3.w);
    *(float4*)(g_KV + i) = r;
}

// ---------------------------------------------------------------------------
// Kernel 3: R = phi_q (1024x256) @ KVcat (256x4096), permuted write + p bias.
// grid = (8, 32, 2).  out[b, w*256+n*16+m, d] = R[w*16+n][m*256+d] + p
// ---------------------------------------------------------------------------
__global__ __launch_bounds__(256) void att_kernel(
    const float* __restrict__ embed, const float* __restrict__ Wp,
    const float* __restrict__ bp, float* __restrict__ out)
{
    __shared__ __align__(16) float As[BK][132];
    __shared__ __align__(16) float Bs[BK][128];
    const int tid = threadIdx.x;
    const int tx = tid & 15, ty = tid >> 4;
    const int b = blockIdx.z;
    const int r0 = blockIdx.x * 128;
    const int j0 = blockIdx.y * 128;
    const float* A    = g_phiQ + (long)b * 1024 * 256 + (long)r0 * 256;
    const float* Bmat = g_KV + (long)b * 256 * 4096;

    ACC_INIT();

    for (int k0 = 0; k0 < 256; k0 += BK) {
#pragma unroll
        for (int i = 0; i < 2; i++) {
            int f4 = tid + i * 256;
            int row = f4 >> 2, kc = (f4 & 3) * 4;
            float4 v = *(const float4*)(A + row * 256 + k0 + kc);
            As[kc + 0][row] = v.x; As[kc + 1][row] = v.y;
            As[kc + 2][row] = v.z; As[kc + 3][row] = v.w;
        }
#pragma unroll
        for (int i = 0; i < 2; i++) {
            int f4 = tid + i * 256;
            int kr = f4 >> 5, nc = (f4 & 31) * 4;
            *(float4*)&Bs[kr][nc] =
                *(const float4*)(Bmat + (long)(k0 + kr) * 4096 + j0 + nc);
        }
        __syncthreads();
        INNER_PRODUCT2();
        __syncthreads();
    }

    const float wp0 = Wp[0], wp1 = Wp[1], wp2 = Wp[2], bpv = bp[0];
    const int jb = j0 + tx * 8;      // column within [0,4096)
    const int m = jb >> 8;           // constant per thread (tile within one m)
    const int d = jb & 255;
#pragma unroll
    for (int i = 0; i < 8; i++) {
        int r = r0 + ty * 8 + i;
        int w = r >> 4, n = r & 15;
        const float* e = embed + ((((long)b * 1024 + w) * 16 + n) * 16 + m) * 3;
        float p = e[0] * wp0 + e[1] * wp1 + e[2] * wp2 + bpv;
        long t = (long)w * 256 + n * 16 + m;
        float* dst = out + ((long)b * 16384 + t) * 256 + d;
        float o[8];
        UNPACK_ROW(i, o);
#pragma unroll
        for (int j = 0; j < 8; j++) o[j] += p;
        *(float4*)(dst)     = *(float4*)&o[0];
        *(float4*)(dst + 4) = *(float4*)&o[4];
    }
}

// ---------------------------------------------------------------------------
// Inputs (metadata order): input, embed_qk, Wq, bq, Wk, bk, Wp, bp
// ---------------------------------------------------------------------------
extern "C" void kernel_launch(void* const* d_in, const int* in_sizes, int n_in,
                              void* d_out, int out_size)
{
    const float* input = (const float*)d_in[0];
    const float* embed = (const float*)d_in[1];
    const float* Wq    = (const float*)d_in[2];
    const float* bq    = (const float*)d_in[3];
    const float* Wk    = (const float*)d_in[4];
    const float* bk    = (const float*)d_in[5];
    const float* Wp    = (const float*)d_in[6];
    const float* bp    = (const float*)d_in[7];
    float* out = (float*)d_out;

    // phi_k (all tokens) + phi_q (first 1024/batch) in one launch
    gemm_act_kernel<<<dim3(136, 2, 2), 256>>>(input, Wk, bk, Wq, bq);
    // KV partials over 4 K-slices (full-chip grid), then reduce
    kv_kernel<<<dim3(2, 2, 128), 256>>>(input);
    kv_reduce_kernel<<<2048, 256>>>();
    // attention GEMM + positional bias + permuted output
    att_kernel<<<dim3(8, 32, 2), 256>>>(embed, Wp, bp, out);
}

// round 4
// speedup vs baseline: 2.0013x; 1.7948x over previous
#include <cuda_runtime.h>
#include <cuda_bf16.h>

// ---------------------------------------------------------------------------
// Round 4: family-portable tensor-core rewrite (tcgen05 unavailable: harness
// compiles via compute_103 virtual arch). mma.sync.m16n8k16 bf16 split-hi/lo
// (3 MMAs: hh + hl + lh), cp.async double-buffered 128x128x32 tiles.
// Token permutation t' = m*1024 + w makes every GEMM K-major contiguous.
//   proj-K : phiKT[b][c][t'] = phi(Wk^T X^T + bk)
//   proj-Q : phiQ [b][r][c]  = phi(X Wq + bq), r<1024
//   kv     : KVT[b][m*256+d][c] = sum_w VT[d][t'] * phiKT[c][t']   (K=1024)
//   att    : out = phiQ @ KVT^T + p, permuted scatter
// ---------------------------------------------------------------------------

typedef unsigned int u32;

// ---------------- device buffers (bf16 hi/lo splits) -----------------------
__device__ __nv_bfloat16 g_Xh[2L * 16384 * 256], g_Xl[2L * 16384 * 256];
__device__ __nv_bfloat16 g_VTh[2L * 256 * 16384], g_VTl[2L * 256 * 16384];
__device__ __nv_bfloat16 g_WkTh[256 * 256], g_WkTl[256 * 256];
__device__ __nv_bfloat16 g_WqTh[256 * 256], g_WqTl[256 * 256];
__device__ __nv_bfloat16 g_PKh[2L * 256 * 16384], g_PKl[2L * 256 * 16384];
__device__ __nv_bfloat16 g_PQh[2L * 1024 * 256], g_PQl[2L * 1024 * 256];
__device__ __nv_bfloat16 g_KVh[2L * 4096 * 256], g_KVl[2L * 4096 * 256];

// ---------------- smem geometry -------------------------------------------
// One stage = 4 tiles (Ah, Al, Bh, Bl), each 128 rows x 32 bf16, row pitch
// 80B (padded: conflict-free ldmatrix, rows r -> banks 20r mod 32).
#define TILE_B   10240                 // 128 * 80
#define STAGE_B  (4 * TILE_B)          // 40960
#define SM_PS    (2 * STAGE_B)         // scratch after both stages
#define SMEM_BYTES (2 * STAGE_B + 1024)

// ---------------- PTX helpers ---------------------------------------------
__device__ __forceinline__ u32 smem_u32(const void* p) {
    u32 a;
    asm("{ .reg .u64 t; cvta.to.shared.u64 t, %1; cvt.u32.u64 %0, t; }"
        : "=r"(a) : "l"(p));
    return a;
}
__device__ __forceinline__ void cp_async16(u32 dst, const void* src) {
    asm volatile("cp.async.cg.shared.global [%0], [%1], 16;"
                 :: "r"(dst), "l"(src));
}
#define CP_COMMIT() asm volatile("cp.async.commit_group;" ::: "memory")
#define CP_WAIT(n)  asm volatile("cp.async.wait_group %0;" :: "n"(n) : "memory")

__device__ __forceinline__ void ldmx4(u32& r0, u32& r1, u32& r2, u32& r3, u32 a) {
    asm volatile("ldmatrix.sync.aligned.m8n8.x4.shared.b16 {%0,%1,%2,%3}, [%4];"
                 : "=r"(r0), "=r"(r1), "=r"(r2), "=r"(r3) : "r"(a));
}
__device__ __forceinline__ void mma_bf16(float* c, const u32* a, const u32* b) {
    asm volatile(
        "mma.sync.aligned.m16n8k16.row.col.f32.bf16.bf16.f32 "
        "{%0,%1,%2,%3}, {%4,%5,%6,%7}, {%8,%9}, {%0,%1,%2,%3};"
        : "+f"(c[0]), "+f"(c[1]), "+f"(c[2]), "+f"(c[3])
        : "r"(a[0]), "r"(a[1]), "r"(a[2]), "r"(a[3]), "r"(b[0]), "r"(b[1]));
}

__device__ __forceinline__ float phi_act(float z) {
    return z > 0.f ? z + 2.f : __expf(z) + 1.f;
}
__device__ __forceinline__ void split1(float x, __nv_bfloat16& h, __nv_bfloat16& l) {
    h = __float2bfloat16(x);
    l = __float2bfloat16(x - __bfloat162float(h));
}
__device__ __forceinline__ u32 pack_bf2(__nv_bfloat16 a, __nv_bfloat16 b) {
    __nv_bfloat162 p; p.x = a; p.y = b;
    return *(u32*)&p;
}

// ---------------------------------------------------------------------------
// Core mainloop: acc(128x128 f32, per-warp 64x32) += A(128xK) * B(128xK)^T
// with split-bf16 3-term products. K = NB*32.
// ---------------------------------------------------------------------------
__device__ __forceinline__ void run_gemm(
    char* sm, u32 smb,
    const __nv_bfloat16* __restrict__ Ah, const __nv_bfloat16* __restrict__ Al, long sA,
    const __nv_bfloat16* __restrict__ Bh, const __nv_bfloat16* __restrict__ Bl, long sB,
    int NB, float acc[4][4][4])
{
    const int tid = threadIdx.x, wid = tid >> 5, lane = tid & 31;
    const int warp_m = (wid & 1) * 64, warp_n = (wid >> 1) * 32;

    auto issue_stage = [&](int s, int kb) {
        u32 base = smb + s * STAGE_B;
#pragma unroll
        for (int i = 0; i < 8; i++) {
            int ch = i * 256 + tid;                // 2048 chunks of 16B
            int tile = ch >> 9, row = (ch >> 2) & 127, kc = ch & 3;
            const __nv_bfloat16* gb =
                (tile == 0) ? Ah : (tile == 1) ? Al : (tile == 2) ? Bh : Bl;
            long st = (tile < 2) ? sA : sB;
            cp_async16(base + tile * TILE_B + row * 80 + kc * 16,
                       gb + (long)row * st + (long)kb * 32 + kc * 8);
        }
        CP_COMMIT();
    };

    issue_stage(0, 0);

    for (int kb = 0; kb < NB; kb++) {
        if (kb + 1 < NB) { issue_stage((kb + 1) & 1, kb + 1); CP_WAIT(1); }
        else             { CP_WAIT(0); }
        __syncthreads();

        u32 sb = smb + (kb & 1) * STAGE_B;
        // A addr: lanes 0-15 rows m0-15 col 0B; 16-31 same rows col 16B
        u32 aAddr = sb + (warp_m + (lane & 15)) * 80 + (lane >> 4) * 16;
        // B addr: block order (n0-7,k0-7)(n0-7,k8-15)(n8-15,k0-7)(n8-15,k8-15)
        u32 bAddr = sb + 2 * TILE_B +
                    (warp_n + (lane & 7) + ((lane >> 4) << 3)) * 80 +
                    ((lane >> 3) & 1) * 16;

#pragma unroll
        for (int kh = 0; kh < 2; kh++) {
            u32 ah[4][4], al[4][4], bh[4][2], bl[4][2];
#pragma unroll
            for (int i = 0; i < 4; i++) {
                ldmx4(ah[i][0], ah[i][1], ah[i][2], ah[i][3],
                      aAddr + i * 16 * 80 + kh * 32);
                ldmx4(al[i][0], al[i][1], al[i][2], al[i][3],
                      aAddr + TILE_B + i * 16 * 80 + kh * 32);
            }
#pragma unroll
            for (int j = 0; j < 2; j++) {
                ldmx4(bh[2 * j][0], bh[2 * j][1], bh[2 * j + 1][0], bh[2 * j + 1][1],
                      bAddr + j * 16 * 80 + kh * 32);
                ldmx4(bl[2 * j][0], bl[2 * j][1], bl[2 * j + 1][0], bl[2 * j + 1][1],
                      bAddr + TILE_B + j * 16 * 80 + kh * 32);
            }
#pragma unroll
            for (int i = 0; i < 4; i++)
#pragma unroll
                for (int j = 0; j < 4; j++) {
                    mma_bf16(acc[i][j], ah[i], bh[j]);
                    mma_bf16(acc[i][j], ah[i], bl[j]);
                    mma_bf16(acc[i][j], al[i], bh[j]);
                }
        }
        __syncthreads();
    }
}

// Store per-warp accumulators into Cs[128][132] f32 (reuses stage memory).
__device__ __forceinline__ void stage_C(char* sm, float acc[4][4][4])
{
    const int tid = threadIdx.x, wid = tid >> 5, lane = tid & 31;
    const int warp_m = (wid & 1) * 64, warp_n = (wid >> 1) * 32;
    float* Cs = (float*)sm;
#pragma unroll
    for (int i = 0; i < 4; i++)
#pragma unroll
        for (int j = 0; j < 4; j++) {
            int r = warp_m + i * 16 + (lane >> 2);
            int c = warp_n + j * 8 + (lane & 3) * 2;
            *(float2*)&Cs[r * 132 + c] =
                make_float2(acc[i][j][0], acc[i][j][1]);
            *(float2*)&Cs[(r + 8) * 132 + c] =
                make_float2(acc[i][j][2], acc[i][j][3]);
        }
    __syncthreads();
}

#define ACC_DECL() float acc[4][4][4];                                   \
    _Pragma("unroll") for (int i = 0; i < 4; i++)                        \
    _Pragma("unroll") for (int j = 0; j < 4; j++)                        \
    _Pragma("unroll") for (int e = 0; e < 4; e++) acc[i][j][e] = 0.f;

// ---------------------------------------------------------------------------
// proj kernel: blockIdx.x<256 -> K-projection (M=c, N=tokens),
//              else            -> Q-projection (M=r, N=c).  K=256 (NB=8).
// ---------------------------------------------------------------------------
__global__ __launch_bounds__(256) void proj_kernel(
    const float* __restrict__ bk, const float* __restrict__ bq)
{
    extern __shared__ char sm[];
    u32 smb = smem_u32(sm);
    const int tid = threadIdx.x;
    const int b = blockIdx.y;
    const bool isK = blockIdx.x < 256;
    int c0, t0 = 0, r0 = 0;
    const __nv_bfloat16 *Ah, *Al, *Bh, *Bl;
    if (isK) {
        c0 = (blockIdx.x >> 7) * 128;
        t0 = (blockIdx.x & 127) * 128;
        Ah = g_WkTh + c0 * 256;  Al = g_WkTl + c0 * 256;
        Bh = g_Xh + ((long)b * 16384 + t0) * 256;
        Bl = g_Xl + ((long)b * 16384 + t0) * 256;
    } else {
        int xi = blockIdx.x - 256;
        r0 = (xi >> 1) * 128;
        c0 = (xi & 1) * 128;
        Ah = g_Xh + ((long)b * 16384 + r0) * 256;
        Al = g_Xl + ((long)b * 16384 + r0) * 256;
        Bh = g_WqTh + c0 * 256;  Bl = g_WqTl + c0 * 256;
    }

    ACC_DECL();
    run_gemm(sm, smb, Ah, Al, 256, Bh, Bl, 256, 8, acc);
    stage_C(sm, acc);
    const float* Cs = (const float*)sm;

    if (isK) {
        const int w0 = t0 >> 4;   // 8 windows in this token tile
#pragma unroll
        for (int it = 0; it < 8; it++) {
            int task = it * 256 + tid;            // 2048 = 128 c x 16 m
            int c = task >> 4, m = task & 15;
            float bias = bk[c0 + c];
            u32 H[4], L[4];
#pragma unroll
            for (int wl = 0; wl < 4; wl++) {
                float x0 = phi_act(Cs[c * 132 + (2 * wl) * 16 + m] + bias);
                float x1 = phi_act(Cs[c * 132 + (2 * wl + 1) * 16 + m] + bias);
                __nv_bfloat16 h0, l0, h1, l1;
                split1(x0, h0, l0); split1(x1, h1, l1);
                H[wl] = pack_bf2(h0, h1); L[wl] = pack_bf2(l0, l1);
            }
            long off = ((long)b * 256 + c0 + c) * 16384 + m * 1024 + w0;
            *(uint4*)(g_PKh + off) = make_uint4(H[0], H[1], H[2], H[3]);
            *(uint4*)(g_PKl + off) = make_uint4(L[0], L[1], L[2], L[3]);
        }
    } else {
#pragma unroll
        for (int it = 0; it < 8; it++) {
            int task = it * 256 + tid;            // 2048 = 128 r x 16 chunks
            int r = task >> 4, ch = task & 15;
            u32 H[4], L[4];
#pragma unroll
            for (int p = 0; p < 4; p++) {
                int col = ch * 8 + 2 * p;
                float x0 = phi_act(Cs[r * 132 + col] + bq[c0 + col]);
                float x1 = phi_act(Cs[r * 132 + col + 1] + bq[c0 + col + 1]);
                __nv_bfloat16 h0, l0, h1, l1;
                split1(x0, h0, l0); split1(x1, h1, l1);
                H[p] = pack_bf2(h0, h1); L[p] = pack_bf2(l0, l1);
            }
            long off = ((long)b * 1024 + r0 + r) * 256 + c0 + ch * 8;
            *(uint4*)(g_PQh + off) = make_uint4(H[0], H[1], H[2], H[3]);
            *(uint4*)(g_PQl + off) = make_uint4(L[0], L[1], L[2], L[3]);
        }
    }
}

// ---------------------------------------------------------------------------
// kv kernel: KVT[b][m*256+d][c] = sum_{t'} VT[d][t'] phiKT[c][t'], K=1024.
// grid (dtile=2, ctile=2, b*16+m), NB=32.
// ---------------------------------------------------------------------------
__global__ __launch_bounds__(256) void kv_kernel()
{
    extern __shared__ char sm[];
    u32 smb = smem_u32(sm);
    const int tid = threadIdx.x;
    const int bm = blockIdx.z, b = bm >> 4, m = bm & 15;
    const int d0 = blockIdx.x * 128, c0 = blockIdx.y * 128;
    const long abase = ((long)b * 256 + d0) * 16384 + m * 1024;
    const long bbase = ((long)b * 256 + c0) * 16384 + m * 1024;

    ACC_DECL();
    run_gemm(sm, smb, g_VTh + abase, g_VTl + abase, 16384,
             g_PKh + bbase, g_PKl + bbase, 16384, 32, acc);
    stage_C(sm, acc);
    const float* Cs = (const float*)sm;

#pragma unroll
    for (int it = 0; it < 8; it++) {
        int task = it * 256 + tid;                // 2048 = 128 d x 16 chunks
        int d = task >> 4, ch = task & 15;
        u32 H[4], L[4];
#pragma unroll
        for (int p = 0; p < 4; p++) {
            float x0 = Cs[d * 132 + ch * 8 + 2 * p];
            float x1 = Cs[d * 132 + ch * 8 + 2 * p + 1];
            __nv_bfloat16 h0, l0, h1, l1;
            split1(x0, h0, l0); split1(x1, h1, l1);
            H[p] = pack_bf2(h0, h1); L[p] = pack_bf2(l0, l1);
        }
        long off = ((long)b * 4096 + m * 256 + d0 + d) * 256 + c0 + ch * 8;
        *(uint4*)(g_KVh + off) = make_uint4(H[0], H[1], H[2], H[3]);
        *(uint4*)(g_KVl + off) = make_uint4(L[0], L[1], L[2], L[3]);
    }
}

// ---------------------------------------------------------------------------
// att kernel: out[b][w*256+n*16+m][d] = sum_c phiQ[r][c] KVT[m*256+d][c] + p.
// grid (rtile=8, jtile=32, b). K=256 (NB=8).
// ---------------------------------------------------------------------------
__global__ __launch_bounds__(256) void att_kernel(
    const float* __restrict__ embed, const float* __restrict__ Wp,
    const float* __restrict__ bp, float* __restrict__ out)
{
    extern __shared__ char sm[];
    u32 smb = smem_u32(sm);
    const int tid = threadIdx.x;
    const int b = blockIdx.z;
    const int r0 = blockIdx.x * 128;
    const int j0 = blockIdx.y * 128;
    const int m = j0 >> 8, d0 = j0 & 255;
    const long abase = ((long)b * 1024 + r0) * 256;
    const long bbase = ((long)b * 4096 + j0) * 256;

    if (tid < 128) {
        int r = r0 + tid, w = r >> 4, n = r & 15;
        const float* e = embed + ((((long)b * 1024 + w) * 16 + n) * 16 + m) * 3;
        ((float*)(sm + SM_PS))[tid] =
            e[0] * Wp[0] + e[1] * Wp[1] + e[2] * Wp[2] + bp[0];
    }

    ACC_DECL();
    run_gemm(sm, smb, g_PQh + abase, g_PQl + abase, 256,
             g_KVh + bbase, g_KVl + bbase, 256, 8, acc);
    stage_C(sm, acc);
    const float* Cs = (const float*)sm;

#pragma unroll
    for (int it = 0; it < 16; it++) {
        int task = it * 256 + tid;                // 4096 = 128 r x 32 f4-chunks
        int r = task >> 5, ch = task & 31;
        float4 v = *(const float4*)&Cs[r * 132 + ch * 4];
        float p = ((const float*)(sm + SM_PS))[r];
        v.x += p; v.y += p; v.z += p; v.w += p;
        int rg = r0 + r, w = rg >> 4, n = rg & 15;
        long t = (long)w * 256 + n * 16 + m;
        *(float4*)(out + ((long)b * 16384 + t) * 256 + d0 + ch * 4) = v;
    }
}

// ---------------------------------------------------------------------------
// prep kernels
// ---------------------------------------------------------------------------
__global__ __launch_bounds__(256) void prep_split(const float* __restrict__ X)
{
    long i = (long)blockIdx.x * 256 + threadIdx.x;   // float4 index
    float4 v = ((const float4*)X)[i];
    __nv_bfloat16 h0, l0, h1, l1, h2, l2, h3, l3;
    split1(v.x, h0, l0); split1(v.y, h1, l1);
    split1(v.z, h2, l2); split1(v.w, h3, l3);
    ((uint2*)g_Xh)[i] = make_uint2(pack_bf2(h0, h1), pack_bf2(h2, h3));
    ((uint2*)g_Xl)[i] = make_uint2(pack_bf2(l0, l1), pack_bf2(l2, l3));
}

// VT[b][d][m*1024+w] = X[b][w*16+m][d]; grid (wtile=32, dtile=8, b*16+m)
__global__ __launch_bounds__(256) void prep_vt(const float* __restrict__ X)
{
    __shared__ float tile[32][33];
    const int bm = blockIdx.z, b = bm >> 4, m = bm & 15;
    const int w0 = blockIdx.x * 32, d0 = blockIdx.y * 32;
    const int dx = threadIdx.x & 31, dy = threadIdx.x >> 5;
#pragma unroll
    for (int p = 0; p < 4; p++) {
        int w = w0 + dy + p * 8;
        tile[dy + p * 8][dx] =
            X[((long)b * 16384 + (long)w * 16 + m) * 256 + d0 + dx];
    }
    __syncthreads();
#pragma unroll
    for (int p = 0; p < 4; p++) {
        int d = d0 + dy + p * 8;
        float v = tile[dx][dy + p * 8];
        __nv_bfloat16 h, l; split1(v, h, l);
        long off = ((long)b * 256 + d) * 16384 + m * 1024 + w0 + dx;
        g_VTh[off] = h; g_VTl[off] = l;
    }
}

// WT[n][k] = W[k][n]; grid (ktile=8, ntile=8, 2: 0=Wk,1=Wq)
__global__ __launch_bounds__(256) void prep_w(
    const float* __restrict__ Wk, const float* __restrict__ Wq)
{
    __shared__ float tile[32][33];
    const int isQ = blockIdx.z;
    const float* W = isQ ? Wq : Wk;
    __nv_bfloat16* TH = isQ ? g_WqTh : g_WkTh;
    __nv_bfloat16* TL = isQ ? g_WqTl : g_WkTl;
    const int k0 = blockIdx.x * 32, n0 = blockIdx.y * 32;
    const int dx = threadIdx.x & 31, dy = threadIdx.x >> 5;
#pragma unroll
    for (int p = 0; p < 4; p++)
        tile[dy + p * 8][dx] = W[(k0 + dy + p * 8) * 256 + n0 + dx];
    __syncthreads();
#pragma unroll
    for (int p = 0; p < 4; p++) {
        float v = tile[dx][dy + p * 8];
        __nv_bfloat16 h, l; split1(v, h, l);
        int off = (n0 + dy + p * 8) * 256 + k0 + dx;
        TH[off] = h; TL[off] = l;
    }
}

// ---------------------------------------------------------------------------
// Inputs (metadata order): input, embed_qk, Wq, bq, Wk, bk, Wp, bp
// ---------------------------------------------------------------------------
extern "C" void kernel_launch(void* const* d_in, const int* in_sizes, int n_in,
                              void* d_out, int out_size)
{
    const float* input = (const float*)d_in[0];
    const float* embed = (const float*)d_in[1];
    const float* Wq    = (const float*)d_in[2];
    const float* bq    = (const float*)d_in[3];
    const float* Wk    = (const float*)d_in[4];
    const float* bk    = (const float*)d_in[5];
    const float* Wp    = (const float*)d_in[6];
    const float* bp    = (const float*)d_in[7];
    float* out = (float*)d_out;

    cudaFuncSetAttribute(proj_kernel, cudaFuncAttributeMaxDynamicSharedMemorySize, SMEM_BYTES);
    cudaFuncSetAttribute(kv_kernel,   cudaFuncAttributeMaxDynamicSharedMemorySize, SMEM_BYTES);
    cudaFuncSetAttribute(att_kernel,  cudaFuncAttributeMaxDynamicSharedMemorySize, SMEM_BYTES);

    prep_split<<<8192, 256>>>(input);
    prep_vt<<<dim3(32, 8, 32), 256>>>(input);
    prep_w<<<dim3(8, 8, 2), 256>>>(Wk, Wq);

    proj_kernel<<<dim3(272, 2), 256, SMEM_BYTES>>>(bk, bq);
    kv_kernel<<<dim3(2, 2, 32), 256, SMEM_BYTES>>>();
    att_kernel<<<dim3(8, 32, 2), 256, SMEM_BYTES>>>(embed, Wp, bp, out);
}